// round 7
// baseline (speedup 1.0000x reference)
#include <cuda_runtime.h>
#include <cuda_bf16.h>
#include <stdint.h>
#include <math.h>

// ---------------- problem constants ----------------
#define B_    256
#define D_    2048
#define N_    65536
#define C_    8192
#define TEMP_ 0.05f

// ---------------- GEMM tiling (bf16, 64x64 warp tiles) ----------------
#define BM 256
#define BN 128
#define BK 32
#define BKPB 80                   // padded row stride in BYTES (40 bf16) — conflict-free
#define KT (D_ / BK)              // 64
#define NTHREADS 256
#define A_TILE_BYTES (BM * BKPB)  // 20480 / stage
#define B_TILE_BYTES (BN * BKPB)  // 10240 / stage
#define CTP 129
#define SMEM_BYTES (128 * CTP * 4) // 66048 > 2*(A+B)=61440 -> union fits

#define NPART 32                  // histogram partials
#define HGRID 128                 // k_hist grid (blocks >= NPART only do conv/zero)

// ---------------- device scratch ----------------
__device__ float          g_S[B_ * C_];
__device__ float          g_diag[B_];
__device__ int            g_part[C_ * NPART];
__device__ int            g_counts[C_];
__device__ int            g_offsets[C_];
__device__ int            g_cursor[C_];
__device__ int            g_perm[N_];
__device__ int            g_clab[N_];
__device__ int            g_targets[B_];
__device__ __nv_bfloat16  g_Abf[B_ * D_];
__device__ float          g_lossb[B_];

// ---------------- helpers ----------------
__device__ __forceinline__ uint32_t smem_u32(const void* p) {
    uint32_t a;
    asm("{ .reg .u64 t; cvta.to.shared.u64 t, %1; cvt.u32.u64 %0, t; }" : "=r"(a) : "l"(p));
    return a;
}
__device__ __forceinline__ void cp_async16(uint32_t sdst, const void* g) {
    asm volatile("cp.async.cg.shared.global [%0], [%1], 16;\n" :: "r"(sdst), "l"(g));
}
#define CP_COMMIT() asm volatile("cp.async.commit_group;\n" ::: "memory")
#define CP_WAIT0()  asm volatile("cp.async.wait_group 0;\n" ::: "memory")

__device__ __forceinline__ void ldsm_x4(uint32_t& r0, uint32_t& r1, uint32_t& r2, uint32_t& r3,
                                        uint32_t addr) {
    asm volatile("ldmatrix.sync.aligned.m8n8.x4.shared.b16 {%0,%1,%2,%3}, [%4];"
                 : "=r"(r0), "=r"(r1), "=r"(r2), "=r"(r3) : "r"(addr));
}
__device__ __forceinline__ void mma16816(float* c,
                                         uint32_t a0, uint32_t a1, uint32_t a2, uint32_t a3,
                                         uint32_t b0, uint32_t b1) {
    asm volatile(
        "mma.sync.aligned.m16n8k16.row.col.f32.bf16.bf16.f32 "
        "{%0,%1,%2,%3}, {%4,%5,%6,%7}, {%8,%9}, {%0,%1,%2,%3};\n"
        : "+f"(c[0]), "+f"(c[1]), "+f"(c[2]), "+f"(c[3])
        : "r"(a0), "r"(a1), "r"(a2), "r"(a3), "r"(b0), "r"(b1));
}
__device__ __forceinline__ void store_b16(uint32_t sdst, float4 f0, float4 f1,
                                          float4 f2, float4 f3) {
    __nv_bfloat162 h0 = __floats2bfloat162_rn(f0.x, f0.y);
    __nv_bfloat162 h1 = __floats2bfloat162_rn(f0.z, f0.w);
    __nv_bfloat162 h2 = __floats2bfloat162_rn(f1.x, f1.y);
    __nv_bfloat162 h3 = __floats2bfloat162_rn(f1.z, f1.w);
    __nv_bfloat162 h4 = __floats2bfloat162_rn(f2.x, f2.y);
    __nv_bfloat162 h5 = __floats2bfloat162_rn(f2.z, f2.w);
    __nv_bfloat162 h6 = __floats2bfloat162_rn(f3.x, f3.y);
    __nv_bfloat162 h7 = __floats2bfloat162_rn(f3.z, f3.w);
    asm volatile("st.shared.v4.b32 [%0], {%1,%2,%3,%4};"
                 :: "r"(sdst), "r"(*(uint32_t*)&h0), "r"(*(uint32_t*)&h1),
                    "r"(*(uint32_t*)&h2), "r"(*(uint32_t*)&h3) : "memory");
    asm volatile("st.shared.v4.b32 [%0], {%1,%2,%3,%4};"
                 :: "r"(sdst + 16), "r"(*(uint32_t*)&h4), "r"(*(uint32_t*)&h5),
                    "r"(*(uint32_t*)&h6), "r"(*(uint32_t*)&h7) : "memory");
}

// ---------------- launch #1: partial hist + conv + zero + targets ----------------
__global__ void __launch_bounds__(256) k_hist(const float* __restrict__ inputs,
                                              const int* __restrict__ labels,
                                              const int* __restrict__ indexes) {
    __shared__ int h[C_];
    int t = threadIdx.x, blk = blockIdx.x;
    int gt = blk * 256 + t;
    if (blk < NPART) {
        for (int i = t; i < C_; i += 256) h[i] = 0;
        __syncthreads();
        int base = blk * (N_ / NPART);
        for (int i = t; i < N_ / NPART; i += 256)
            atomicAdd(&h[labels[base + i]], 1);
        __syncthreads();
        for (int i = t; i < C_; i += 256) g_part[i * NPART + blk] = h[i];
    }
    // conv A to bf16 (vectorized: float4 -> 2x bf162)
    const float4* in4 = (const float4*)inputs;
    uint2* out8 = (uint2*)g_Abf;
    for (int i = gt; i < B_ * D_ / 4; i += HGRID * 256) {
        float4 v = in4[i];
        __nv_bfloat162 a = __floats2bfloat162_rn(v.x, v.y);
        __nv_bfloat162 b = __floats2bfloat162_rn(v.z, v.w);
        uint2 u = { *(uint32_t*)&a, *(uint32_t*)&b };
        out8[i] = u;
    }
    // zero S / diag
    float4 z4 = { 0.f, 0.f, 0.f, 0.f };
    float4* S4 = (float4*)g_S;
    for (int i = gt; i < B_ * C_ / 4; i += HGRID * 256) S4[i] = z4;
    if (gt < B_) { g_diag[gt] = 0.f; g_targets[gt] = labels[indexes[gt]]; }
}

// ---------------- launch #2: counts, offsets, cursor ----------------
__global__ void k_scan() {
    __shared__ int part[256];
    int t = threadIdx.x;
    int base = t * 32;
    int loc[32];
    int s = 0;
#pragma unroll
    for (int i = 0; i < 32; i++) {
        int c = base + i;
        int cnt = 0;
        const int4* pp = (const int4*)(g_part + c * NPART);
#pragma unroll
        for (int q = 0; q < NPART / 4; q++) {
            int4 v = pp[q];
            cnt += v.x + v.y + v.z + v.w;
        }
        g_counts[c] = cnt;
        loc[i] = s;
        s += cnt;
    }
    part[t] = s;
    __syncthreads();
    int own = s;
    for (int off = 1; off < 256; off <<= 1) {
        int v = (t >= off) ? part[t - off] : 0;
        __syncthreads();
        part[t] += v;
        __syncthreads();
    }
    int excl = part[t] - own;
#pragma unroll
    for (int i = 0; i < 32; i++) {
        g_offsets[base + i] = excl + loc[i];
        g_cursor[base + i] = 0;
    }
}

// ---------------- launch #3: scatter ----------------
__global__ void k_scatter(const int* __restrict__ labels) {
    int n = blockIdx.x * blockDim.x + threadIdx.x;
    if (n < N_) {
        int c = labels[n];
        int p = g_offsets[c] + atomicAdd(&g_cursor[c], 1);
        g_perm[p] = n;
        g_clab[p] = c;
    }
}

// ---------------- launch #4: GEMM (64x64 warp tiles) + segmented reduction -------
__global__ void __launch_bounds__(NTHREADS, 1) k_gemm(const float* __restrict__ features) {
    extern __shared__ char smem[];
    uint8_t* As = (uint8_t*)smem;
    uint8_t* Bs = As + 2 * A_TILE_BYTES;
    __shared__ int s_perm[BN];
    __shared__ int s_clab[BN];

    int tid = threadIdx.x;
    int jb = blockIdx.x * BN;
    if (tid < BN) { s_perm[tid] = g_perm[jb + tid]; s_clab[tid] = g_clab[jb + tid]; }
    __syncthreads();

    int lane = tid & 31, w = tid >> 5;
    int wm = (w >> 1) * 64;      // 4 warps along M
    int wn = (w & 1) * 64;       // 2 warps along N
    int g = lane >> 2, tg = lane & 3;

    uint32_t sbA = smem_u32(As);
    uint32_t sbB = smem_u32(Bs);
    uint32_t adA = sbA + (uint32_t)(wm + (lane & 15)) * BKPB + ((lane & 16) ? 16 : 0);
    uint32_t adB = sbB + (uint32_t)(wn + (lane & 7) + ((lane & 16) ? 8 : 0)) * BKPB
                       + ((lane & 8) ? 16 : 0);

    // staging roles
    const __nv_bfloat16* Ag = g_Abf + (size_t)tid * D_;          // 1 A row / thread
    uint32_t adStA = sbA + (uint32_t)tid * BKPB;
    int brow = tid >> 1, bh = tid & 1;                           // 2 threads / B row
    const float* Bg = features + (size_t)s_perm[brow] * (size_t)D_ + bh * 16;
    uint32_t adStB = sbB + (uint32_t)brow * BKPB + bh * 32;

    float acc[4][8][4];
#pragma unroll
    for (int mi = 0; mi < 4; mi++)
#pragma unroll
        for (int ni = 0; ni < 8; ni++)
#pragma unroll
            for (int q = 0; q < 4; q++) acc[mi][ni][q] = 0.f;

    float4 f0, f1, f2, f3;
    {   // prologue
        cp_async16(adStA,      Ag);
        cp_async16(adStA + 16, Ag + 8);
        cp_async16(adStA + 32, Ag + 16);
        cp_async16(adStA + 48, Ag + 24);
        CP_COMMIT();
        f0 = *(const float4*)(Bg);
        f1 = *(const float4*)(Bg + 4);
        f2 = *(const float4*)(Bg + 8);
        f3 = *(const float4*)(Bg + 12);
        store_b16(adStB, f0, f1, f2, f3);
        CP_WAIT0();
    }
    __syncthreads();

    for (int kt = 0; kt < KT; ++kt) {
        int nxt = kt + 1;
        uint32_t aA = adA + (kt & 1) * A_TILE_BYTES;
        uint32_t aB = adB + (kt & 1) * B_TILE_BYTES;

        if (nxt < KT) {
            int k0 = nxt * BK;
            uint32_t ad = adStA + (nxt & 1) * A_TILE_BYTES;
            cp_async16(ad,      Ag + k0);
            cp_async16(ad + 16, Ag + k0 + 8);
            cp_async16(ad + 32, Ag + k0 + 16);
            cp_async16(ad + 48, Ag + k0 + 24);
            CP_COMMIT();
            f0 = *(const float4*)(Bg + k0);
            f1 = *(const float4*)(Bg + k0 + 4);
            f2 = *(const float4*)(Bg + k0 + 8);
            f3 = *(const float4*)(Bg + k0 + 12);
        }

#pragma unroll
        for (int ks = 0; ks < 2; ks++) {
            uint32_t bF0[8], bF1[8];
#pragma unroll
            for (int nb = 0; nb < 4; nb++)
                ldsm_x4(bF0[2 * nb], bF1[2 * nb], bF0[2 * nb + 1], bF1[2 * nb + 1],
                        aB + nb * (16 * BKPB) + ks * 32);
#pragma unroll
            for (int mi = 0; mi < 4; mi++) {
                uint32_t a0, a1, a2, a3;
                ldsm_x4(a0, a1, a2, a3, aA + mi * (16 * BKPB) + ks * 32);
#pragma unroll
                for (int ni = 0; ni < 8; ni++)
                    mma16816(acc[mi][ni], a0, a1, a2, a3, bF0[ni], bF1[ni]);
            }
        }

        if (nxt < KT)
            store_b16(adStB + (nxt & 1) * B_TILE_BYTES, f0, f1, f2, f3);
        CP_WAIT0();
        __syncthreads();
    }

    // ---- epilogue: two 128-row halves through the 66 KB smem union ----
    float* Ct = (float*)smem;
    int erow = tid >> 1;
    int ehalf = tid & 1;
#pragma unroll
    for (int half = 0; half < 2; half++) {
        if ((wm >> 7) == half) {
            int r0 = wm - half * 128;
#pragma unroll
            for (int mi = 0; mi < 4; mi++) {
                int r = r0 + mi * 16 + g;
#pragma unroll
                for (int ni = 0; ni < 8; ni++) {
                    int c = wn + ni * 8 + 2 * tg;
                    Ct[r * CTP + c]           = acc[mi][ni][0];
                    Ct[r * CTP + c + 1]       = acc[mi][ni][1];
                    Ct[(r + 8) * CTP + c]     = acc[mi][ni][2];
                    Ct[(r + 8) * CTP + c + 1] = acc[mi][ni][3];
                }
            }
        }
        __syncthreads();

        int b = half * 128 + erow;
        int tb = g_targets[b];
        const float* row = Ct + erow * CTP + ehalf * 64;
        const int* cl = s_clab + ehalf * 64;
        float run = 0.f, run2 = 0.f;
        int cur = cl[0];
#pragma unroll 8
        for (int j = 0; j < 64; j++) {
            int c = cl[j];
            float v = row[j];
            if (c != cur) {
                atomicAdd(&g_S[b * C_ + cur], run);
                if (cur == tb) atomicAdd(&g_diag[b], run2);
                run = 0.f; run2 = 0.f; cur = c;
            }
            run += v;
            if (c == tb) run2 += v * v;
        }
        atomicAdd(&g_S[b * C_ + cur], run);
        if (cur == tb) atomicAdd(&g_diag[b], run2);
        __syncthreads();
    }
}

// ---------------- masked softmax + NLL ----------------
__global__ void k_softmax() {
    int b = blockIdx.x, t = threadIdx.x;
    int tb = g_targets[b];
    const float* Srow = g_S + b * C_;
    float dg = g_diag[b] * (1.f / TEMP_);
    __shared__ float s_et;
    __shared__ float red[256];
    float denom = 0.f;
    for (int c = t; c < C_; c += 256) {
        int cnt = g_counts[c];
        float e = 0.f;
        if (cnt > 0) {
            float sim = (c == tb) ? dg : (Srow[c] * (1.f / TEMP_) / (float)cnt);
            e = expf(sim);
            if (c == tb) s_et = e;
        }
        denom += e;
    }
    red[t] = denom;
    __syncthreads();
    for (int o = 128; o > 0; o >>= 1) {
        if (t < o) red[t] += red[t + o];
        __syncthreads();
    }
    if (t == 0) {
        float p = s_et / (red[0] + 1e-6f) + 1e-6f;
        g_lossb[b] = -logf(p);
    }
}
__global__ void k_loss(float* __restrict__ out) {
    int t = threadIdx.x;
    __shared__ float red[256];
    red[t] = g_lossb[t];
    __syncthreads();
    for (int o = 128; o > 0; o >>= 1) {
        if (t < o) red[t] += red[t + o];
        __syncthreads();
    }
    if (t == 0) out[0] = red[0] / (float)B_;
}

// ---------------- launch ----------------
extern "C" void kernel_launch(void* const* d_in, const int* in_sizes, int n_in,
                              void* d_out, int out_size) {
    const float* inputs   = (const float*)d_in[0];
    const int*   indexes  = (const int*)d_in[1];
    const float* features = (const float*)d_in[2];
    const int*   labels   = (const int*)d_in[3];
    float*       out      = (float*)d_out;
    (void)in_sizes; (void)n_in; (void)out_size;

    cudaFuncSetAttribute(k_gemm, cudaFuncAttributeMaxDynamicSharedMemorySize, SMEM_BYTES);

    k_hist<<<HGRID, 256>>>(inputs, labels, indexes);      // launch 1
    k_scan<<<1, 256>>>();                                 // launch 2
    k_scatter<<<N_ / 256, 256>>>(labels);                 // launch 3
    k_gemm<<<N_ / BN, NTHREADS, SMEM_BYTES>>>(features);  // launch 4 (profiled slot)
    k_softmax<<<B_, 256>>>();                             // launch 5
    k_loss<<<1, 256>>>(out);                              // launch 6
}

// round 8
// speedup vs baseline: 1.2865x; 1.2865x over previous
#include <cuda_runtime.h>
#include <cuda_bf16.h>
#include <stdint.h>
#include <math.h>

// ---------------- problem constants ----------------
#define B_    256
#define D_    2048
#define N_    65536
#define C_    8192
#define TEMP_ 0.05f

// ---------------- GEMM tiling (bf16, 64x32 warp tiles, 4x4 warp grid) ----------
#define BM 256
#define BN 128
#define BK 64
#define BKPB 144                  // padded row stride in BYTES (128B data + 16B pad)
#define KT (D_ / BK)              // 32
#define NTHREADS 512
#define A_TILE_BYTES (BM * BKPB)  // 36864 / stage
#define B_TILE_BYTES (BN * BKPB)  // 18432 / stage
#define CTP 129
#define SMEM_BYTES (2 * (A_TILE_BYTES + B_TILE_BYTES))  // 110592 > 66048 epilogue

#define NPART 4                   // histogram partials
#define HGRID 128

// ---------------- device scratch ----------------
__device__ float          g_S[B_ * C_];
__device__ float          g_diag[B_];
__device__ int            g_part[C_ * NPART];
__device__ int            g_counts[C_];
__device__ int            g_offsets[C_];
__device__ int            g_cursor[C_];
__device__ int            g_perm[N_];
__device__ int            g_clab[N_];
__device__ int            g_targets[B_];
__device__ __nv_bfloat16  g_Abf[B_ * D_];
__device__ float          g_lossb[B_];

// ---------------- helpers ----------------
__device__ __forceinline__ uint32_t smem_u32(const void* p) {
    uint32_t a;
    asm("{ .reg .u64 t; cvta.to.shared.u64 t, %1; cvt.u32.u64 %0, t; }" : "=r"(a) : "l"(p));
    return a;
}
__device__ __forceinline__ void cp_async16(uint32_t sdst, const void* g) {
    asm volatile("cp.async.cg.shared.global [%0], [%1], 16;\n" :: "r"(sdst), "l"(g));
}
#define CP_COMMIT() asm volatile("cp.async.commit_group;\n" ::: "memory")
#define CP_WAIT0()  asm volatile("cp.async.wait_group 0;\n" ::: "memory")

__device__ __forceinline__ void ldsm_x4(uint32_t& r0, uint32_t& r1, uint32_t& r2, uint32_t& r3,
                                        uint32_t addr) {
    asm volatile("ldmatrix.sync.aligned.m8n8.x4.shared.b16 {%0,%1,%2,%3}, [%4];"
                 : "=r"(r0), "=r"(r1), "=r"(r2), "=r"(r3) : "r"(addr));
}
__device__ __forceinline__ void mma16816(float* c,
                                         uint32_t a0, uint32_t a1, uint32_t a2, uint32_t a3,
                                         uint32_t b0, uint32_t b1) {
    asm volatile(
        "mma.sync.aligned.m16n8k16.row.col.f32.bf16.bf16.f32 "
        "{%0,%1,%2,%3}, {%4,%5,%6,%7}, {%8,%9}, {%0,%1,%2,%3};\n"
        : "+f"(c[0]), "+f"(c[1]), "+f"(c[2]), "+f"(c[3])
        : "r"(a0), "r"(a1), "r"(a2), "r"(a3), "r"(b0), "r"(b1));
}
__device__ __forceinline__ void store_b16(uint32_t sdst, float4 f0, float4 f1,
                                          float4 f2, float4 f3) {
    __nv_bfloat162 h0 = __floats2bfloat162_rn(f0.x, f0.y);
    __nv_bfloat162 h1 = __floats2bfloat162_rn(f0.z, f0.w);
    __nv_bfloat162 h2 = __floats2bfloat162_rn(f1.x, f1.y);
    __nv_bfloat162 h3 = __floats2bfloat162_rn(f1.z, f1.w);
    __nv_bfloat162 h4 = __floats2bfloat162_rn(f2.x, f2.y);
    __nv_bfloat162 h5 = __floats2bfloat162_rn(f2.z, f2.w);
    __nv_bfloat162 h6 = __floats2bfloat162_rn(f3.x, f3.y);
    __nv_bfloat162 h7 = __floats2bfloat162_rn(f3.z, f3.w);
    asm volatile("st.shared.v4.b32 [%0], {%1,%2,%3,%4};"
                 :: "r"(sdst), "r"(*(uint32_t*)&h0), "r"(*(uint32_t*)&h1),
                    "r"(*(uint32_t*)&h2), "r"(*(uint32_t*)&h3) : "memory");
    asm volatile("st.shared.v4.b32 [%0], {%1,%2,%3,%4};"
                 :: "r"(sdst + 16), "r"(*(uint32_t*)&h4), "r"(*(uint32_t*)&h5),
                    "r"(*(uint32_t*)&h6), "r"(*(uint32_t*)&h7) : "memory");
}

// ---------------- launch #1: partial hist + conv + zero + targets ----------------
__global__ void __launch_bounds__(256) k_hist(const float* __restrict__ inputs,
                                              const int* __restrict__ labels,
                                              const int* __restrict__ indexes) {
    __shared__ int h[C_];
    int t = threadIdx.x, blk = blockIdx.x;
    int gt = blk * 256 + t;
    if (blk < NPART) {
        for (int i = t; i < C_; i += 256) h[i] = 0;
        __syncthreads();
        int base = blk * (N_ / NPART);
        for (int i = t; i < N_ / NPART; i += 256)
            atomicAdd(&h[labels[base + i]], 1);
        __syncthreads();
        for (int i = t; i < C_; i += 256) g_part[i * NPART + blk] = h[i];
    }
    const float4* in4 = (const float4*)inputs;
    uint2* out8 = (uint2*)g_Abf;
    for (int i = gt; i < B_ * D_ / 4; i += HGRID * 256) {
        float4 v = in4[i];
        __nv_bfloat162 a = __floats2bfloat162_rn(v.x, v.y);
        __nv_bfloat162 b = __floats2bfloat162_rn(v.z, v.w);
        uint2 u = { *(uint32_t*)&a, *(uint32_t*)&b };
        out8[i] = u;
    }
    float4 z4 = { 0.f, 0.f, 0.f, 0.f };
    float4* S4 = (float4*)g_S;
    for (int i = gt; i < B_ * C_ / 4; i += HGRID * 256) S4[i] = z4;
    if (gt < B_) { g_diag[gt] = 0.f; g_targets[gt] = labels[indexes[gt]]; }
}

// ---------------- launch #2: counts, offsets, cursor ----------------
__global__ void k_scan() {
    __shared__ int part[256];
    int t = threadIdx.x;
    int base = t * 32;
    int loc[32];
    int s = 0;
#pragma unroll
    for (int i = 0; i < 32; i++) {
        int4 v = *(const int4*)(g_part + (base + i) * NPART);
        int cnt = v.x + v.y + v.z + v.w;
        g_counts[base + i] = cnt;
        loc[i] = s;
        s += cnt;
    }
    part[t] = s;
    __syncthreads();
    int own = s;
    for (int off = 1; off < 256; off <<= 1) {
        int v = (t >= off) ? part[t - off] : 0;
        __syncthreads();
        part[t] += v;
        __syncthreads();
    }
    int excl = part[t] - own;
#pragma unroll
    for (int i = 0; i < 32; i++) {
        g_offsets[base + i] = excl + loc[i];
        g_cursor[base + i] = 0;
    }
}

// ---------------- launch #3: scatter ----------------
__global__ void k_scatter(const int* __restrict__ labels) {
    int n = blockIdx.x * blockDim.x + threadIdx.x;
    if (n < N_) {
        int c = labels[n];
        int p = g_offsets[c] + atomicAdd(&g_cursor[c], 1);
        g_perm[p] = n;
        g_clab[p] = c;
    }
}

// ---------------- launch #4: GEMM + fused segmented reduction ----------------
__global__ void __launch_bounds__(NTHREADS, 1) k_gemm(const float* __restrict__ features) {
    extern __shared__ char smem[];
    uint8_t* As = (uint8_t*)smem;
    uint8_t* Bs = As + 2 * A_TILE_BYTES;
    __shared__ int s_perm[BN];
    __shared__ int s_clab[BN];

    int tid = threadIdx.x;
    int jb = blockIdx.x * BN;
    if (tid < BN) { s_perm[tid] = g_perm[jb + tid]; s_clab[tid] = g_clab[jb + tid]; }
    __syncthreads();

    int lane = tid & 31, w = tid >> 5;
    int wm = (w >> 2) * 64;      // 4 warps along M
    int wn = (w & 3) * 32;       // 4 warps along N
    int g = lane >> 2, tg = lane & 3;

    uint32_t sbA = smem_u32(As);
    uint32_t sbB = smem_u32(Bs);
    uint32_t adA = sbA + (uint32_t)(wm + (lane & 15)) * BKPB + ((lane & 16) ? 16 : 0);
    uint32_t adB = sbB + (uint32_t)(wn + (lane & 7) + ((lane & 16) ? 8 : 0)) * BKPB
                       + ((lane & 8) ? 16 : 0);

    // staging roles
    int arow = tid >> 1, ah = tid & 1;                           // 2 threads / A row, 64B each
    const __nv_bfloat16* Ag = g_Abf + (size_t)arow * D_ + ah * 32;
    uint32_t adStA = sbA + (uint32_t)arow * BKPB + ah * 64;
    int brow = tid >> 2, bq = tid & 3;                           // 4 threads / B row, 16 f32 each
    const float* Bg = features + (size_t)s_perm[brow] * (size_t)D_ + bq * 16;
    uint32_t adStB = sbB + (uint32_t)brow * BKPB + bq * 32;

    float acc[4][4][4];
#pragma unroll
    for (int mi = 0; mi < 4; mi++)
#pragma unroll
        for (int ni = 0; ni < 4; ni++)
#pragma unroll
            for (int q = 0; q < 4; q++) acc[mi][ni][q] = 0.f;

    float4 f0, f1, f2, f3;
    {   // prologue: stage k-tile 0
        cp_async16(adStA,      Ag);
        cp_async16(adStA + 16, Ag + 8);
        cp_async16(adStA + 32, Ag + 16);
        cp_async16(adStA + 48, Ag + 24);
        CP_COMMIT();
        f0 = *(const float4*)(Bg);
        f1 = *(const float4*)(Bg + 4);
        f2 = *(const float4*)(Bg + 8);
        f3 = *(const float4*)(Bg + 12);
        store_b16(adStB, f0, f1, f2, f3);
        CP_WAIT0();
    }
    __syncthreads();

    for (int kt = 0; kt < KT; ++kt) {
        int nxt = kt + 1;
        uint32_t aA = adA + (kt & 1) * A_TILE_BYTES;
        uint32_t aB = adB + (kt & 1) * B_TILE_BYTES;

        if (nxt < KT) {
            int k0 = nxt * BK;
            uint32_t ad = adStA + (nxt & 1) * A_TILE_BYTES;
            cp_async16(ad,      Ag + k0);
            cp_async16(ad + 16, Ag + k0 + 8);
            cp_async16(ad + 32, Ag + k0 + 16);
            cp_async16(ad + 48, Ag + k0 + 24);
            CP_COMMIT();
            f0 = *(const float4*)(Bg + k0);
            f1 = *(const float4*)(Bg + k0 + 4);
            f2 = *(const float4*)(Bg + k0 + 8);
            f3 = *(const float4*)(Bg + k0 + 12);
        }

#pragma unroll
        for (int ks = 0; ks < 4; ks++) {
            uint32_t bF0[4], bF1[4];
            ldsm_x4(bF0[0], bF1[0], bF0[1], bF1[1], aB + ks * 32);
            ldsm_x4(bF0[2], bF1[2], bF0[3], bF1[3], aB + 16 * BKPB + ks * 32);
#pragma unroll
            for (int mi = 0; mi < 4; mi++) {
                uint32_t a0, a1, a2, a3;
                ldsm_x4(a0, a1, a2, a3, aA + mi * (16 * BKPB) + ks * 32);
#pragma unroll
                for (int ni = 0; ni < 4; ni++)
                    mma16816(acc[mi][ni], a0, a1, a2, a3, bF0[ni], bF1[ni]);
            }
        }

        if (nxt < KT)
            store_b16(adStB + (nxt & 1) * B_TILE_BYTES, f0, f1, f2, f3);
        CP_WAIT0();
        __syncthreads();
    }

    // ---- epilogue: two 128-row halves through the smem union ----
    float* Ct = (float*)smem;
    int erow = tid >> 2;
    int eq = tid & 3;
#pragma unroll
    for (int half = 0; half < 2; half++) {
        if ((wm >> 7) == half) {
            int r0 = wm - half * 128;
#pragma unroll
            for (int mi = 0; mi < 4; mi++) {
                int r = r0 + mi * 16 + g;
#pragma unroll
                for (int ni = 0; ni < 4; ni++) {
                    int c = wn + ni * 8 + 2 * tg;
                    Ct[r * CTP + c]           = acc[mi][ni][0];
                    Ct[r * CTP + c + 1]       = acc[mi][ni][1];
                    Ct[(r + 8) * CTP + c]     = acc[mi][ni][2];
                    Ct[(r + 8) * CTP + c + 1] = acc[mi][ni][3];
                }
            }
        }
        __syncthreads();

        int b = half * 128 + erow;
        int tb = g_targets[b];
        const float* row = Ct + erow * CTP + eq * 32;
        const int* cl = s_clab + eq * 32;
        float run = 0.f, run2 = 0.f;
        int cur = cl[0];
#pragma unroll 8
        for (int j = 0; j < 32; j++) {
            int c = cl[j];
            float v = row[j];
            if (c != cur) {
                atomicAdd(&g_S[b * C_ + cur], run);
                if (cur == tb) atomicAdd(&g_diag[b], run2);
                run = 0.f; run2 = 0.f; cur = c;
            }
            run += v;
            if (c == tb) run2 += v * v;
        }
        atomicAdd(&g_S[b * C_ + cur], run);
        if (cur == tb) atomicAdd(&g_diag[b], run2);
        __syncthreads();
    }
}

// ---------------- masked softmax + NLL ----------------
__global__ void k_softmax() {
    int b = blockIdx.x, t = threadIdx.x;
    int tb = g_targets[b];
    const float* Srow = g_S + b * C_;
    float dg = g_diag[b] * (1.f / TEMP_);
    __shared__ float s_et;
    __shared__ float red[256];
    float denom = 0.f;
    for (int c = t; c < C_; c += 256) {
        int cnt = g_counts[c];
        float e = 0.f;
        if (cnt > 0) {
            float sim = (c == tb) ? dg : (Srow[c] * (1.f / TEMP_) / (float)cnt);
            e = expf(sim);
            if (c == tb) s_et = e;
        }
        denom += e;
    }
    red[t] = denom;
    __syncthreads();
    for (int o = 128; o > 0; o >>= 1) {
        if (t < o) red[t] += red[t + o];
        __syncthreads();
    }
    if (t == 0) {
        float p = s_et / (red[0] + 1e-6f) + 1e-6f;
        g_lossb[b] = -logf(p);
    }
}
__global__ void k_loss(float* __restrict__ out) {
    int t = threadIdx.x;
    __shared__ float red[256];
    red[t] = g_lossb[t];
    __syncthreads();
    for (int o = 128; o > 0; o >>= 1) {
        if (t < o) red[t] += red[t + o];
        __syncthreads();
    }
    if (t == 0) out[0] = red[0] / (float)B_;
}

// ---------------- launch ----------------
extern "C" void kernel_launch(void* const* d_in, const int* in_sizes, int n_in,
                              void* d_out, int out_size) {
    const float* inputs   = (const float*)d_in[0];
    const int*   indexes  = (const int*)d_in[1];
    const float* features = (const float*)d_in[2];
    const int*   labels   = (const int*)d_in[3];
    float*       out      = (float*)d_out;
    (void)in_sizes; (void)n_in; (void)out_size;

    cudaFuncSetAttribute(k_gemm, cudaFuncAttributeMaxDynamicSharedMemorySize, SMEM_BYTES);

    k_hist<<<HGRID, 256>>>(inputs, labels, indexes);      // launch 1
    k_scan<<<1, 256>>>();                                 // launch 2
    k_scatter<<<N_ / 256, 256>>>(labels);                 // launch 3
    k_gemm<<<N_ / BN, NTHREADS, SMEM_BYTES>>>(features);  // launch 4 (profiled slot)
    k_softmax<<<B_, 256>>>();                             // launch 5
    k_loss<<<1, 256>>>(out);                              // launch 6
}